// round 10
// baseline (speedup 1.0000x reference)
#include <cuda_runtime.h>
#include <math.h>

#define BATCH 16
#define DIMC  512
#define RES   1024
#define NHKD  256
#define HQKV  1536
#define DHDIM 1024
#define NHEAD 8
#define KD    32
#define DV    128
#define ATT_SCALE 0.17677669529663687f

// ---------------- scratch (static device globals; no allocations) -------------
__device__ float g_qkv[BATCH * HQKV * RES];
__device__ float g_q  [BATCH * NHKD * RES];
__device__ float g_att[BATCH * DHDIM * RES];

// ---------------- tf32 / cp.async helpers --------------------------------------
__device__ __forceinline__ float f2tf(float x) {
    unsigned r;
    asm("cvt.rna.tf32.f32 %0, %1;" : "=r"(r) : "f"(x));
    return __uint_as_float(r);
}
__device__ __forceinline__ void mma_tf32(float c[4], const float a[4],
                                         float b0, float b1) {
    asm volatile(
        "mma.sync.aligned.m16n8k8.row.col.f32.tf32.tf32.f32 "
        "{%0,%1,%2,%3}, {%4,%5,%6,%7}, {%8,%9}, {%0,%1,%2,%3};"
        : "+f"(c[0]), "+f"(c[1]), "+f"(c[2]), "+f"(c[3])
        : "r"(__float_as_uint(a[0])), "r"(__float_as_uint(a[1])),
          "r"(__float_as_uint(a[2])), "r"(__float_as_uint(a[3])),
          "r"(__float_as_uint(b0)), "r"(__float_as_uint(b1)));
}
#define CP16(dst, src) \
    asm volatile("cp.async.cg.shared.global [%0], [%1], 16;" :: "r"(dst), "l"(src))
#define CP_COMMIT() asm volatile("cp.async.commit_group;")
#define CP_WAIT0()  asm volatile("cp.async.wait_group 0;")
#define CP_WAIT1()  asm volatile("cp.async.wait_group 1;")
#define CP_WAIT2()  asm volatile("cp.async.wait_group 2;")

// ---------------- GEMM (C[b,o,l] = sum_c W[o,c] * X[b,c,l]) + BN ---------------
// tf32 mma, 128x128 tile, K-chunk 16, 256 threads, 4-stage cp.async pipeline.
// A stage: [128 rows][20] ; B stage: [16 k][136] (conflict-free fragment LDS).
#define GSTG_A 2560                 // 128*20
#define GSTG_B 2176                 // 16*136
#define GSTG   (GSTG_A + GSTG_B)
#define GEMM_SMEM_BYTES (4 * GSTG * 4)

__global__ __launch_bounds__(256) void gemm_tf32_bn(
    const float* __restrict__ W, const float* __restrict__ X,
    const float* __restrict__ gg, const float* __restrict__ bb,
    const float* __restrict__ mm, const float* __restrict__ vv,
    float* __restrict__ out, int O, int C, int L)
{
    extern __shared__ __align__(16) float gsh[];
    const unsigned sh_u32 = (unsigned)__cvta_generic_to_shared(gsh);

    const int b  = blockIdx.z;
    const float* Xb = X + (size_t)b * C * L;
    float* Ob = out + (size_t)b * O * L;
    const int o0 = blockIdx.y * 128;
    const int l0 = blockIdx.x * 128;
    const int t = threadIdx.x, lane = t & 31, wid = t >> 5;
    const int wm = wid & 3, wn = wid >> 2;
    const int tig = lane & 3, grp = lane >> 2;

    float acc[2][8][4];
    #pragma unroll
    for (int m = 0; m < 2; m++)
        #pragma unroll
        for (int j = 0; j < 8; j++)
            #pragma unroll
            for (int r = 0; r < 4; r++) acc[m][j][r] = 0.0f;

    auto stage = [&](int k0, int s) {
        unsigned base = sh_u32 + (unsigned)(s * GSTG) * 4u;
        #pragma unroll
        for (int r = 0; r < 2; r++) {               // A: 128 rows x 16 k
            int idx = t + r * 256;
            int row = idx >> 2, kq = (idx & 3) * 4;
            CP16(base + (unsigned)(row * 20 + kq) * 4u,
                 &W[(size_t)(o0 + row) * C + k0 + kq]);
        }
        #pragma unroll
        for (int r = 0; r < 2; r++) {               // B: 16 k x 128 l
            int idx = t + r * 256;
            int k = idx >> 5, m4 = (idx & 31) * 4;
            CP16(base + (unsigned)(GSTG_A + k * 136 + m4) * 4u,
                 &Xb[(size_t)(k0 + k) * L + l0 + m4]);
        }
    };

    const int niter = C / 16;
    stage(0, 0);  CP_COMMIT();
    stage(16, 1); CP_COMMIT();
    stage(32, 2); CP_COMMIT();

    for (int it = 0; it < niter; it++) {
        const int inflight = niter - it;   // groups currently pending (pre-wait)
        if (inflight >= 3)      { CP_WAIT2(); }
        else if (inflight == 2) { CP_WAIT1(); }
        else                    { CP_WAIT0(); }
        __syncthreads();
        if (it + 3 < niter) { stage((it + 3) * 16, (it + 3) & 3); CP_COMMIT(); }

        const float* As = gsh + (it & 3) * GSTG;
        const float* Bs = As + GSTG_A;

        #pragma unroll
        for (int kk = 0; kk < 2; kk++) {
            float a[2][4];
            #pragma unroll
            for (int m = 0; m < 2; m++) {
                const int row = wm * 32 + m * 16 + grp;
                a[m][0] = As[row * 20 + kk * 8 + tig];
                a[m][1] = As[(row + 8) * 20 + kk * 8 + tig];
                a[m][2] = As[row * 20 + kk * 8 + tig + 4];
                a[m][3] = As[(row + 8) * 20 + kk * 8 + tig + 4];
            }
            #pragma unroll
            for (int j = 0; j < 8; j++) {
                const int col = wn * 64 + j * 8 + grp;
                float b0 = Bs[(kk * 8 + tig) * 136 + col];
                float b1 = Bs[(kk * 8 + tig + 4) * 136 + col];
                mma_tf32(acc[0][j], a[0], b0, b1);
                mma_tf32(acc[1][j], a[1], b0, b1);
            }
        }
    }

    #pragma unroll
    for (int m = 0; m < 2; m++) {
        const int r0 = o0 + wm * 32 + m * 16 + grp;
        const int r1 = r0 + 8;
        const float i0 = gg[r0] * rsqrtf(vv[r0] + 1e-5f);
        const float be0 = bb[r0] - mm[r0] * i0;
        const float i1 = gg[r1] * rsqrtf(vv[r1] + 1e-5f);
        const float be1 = bb[r1] - mm[r1] * i1;
        #pragma unroll
        for (int j = 0; j < 8; j++) {
            const int l = l0 + wn * 64 + j * 8 + tig * 2;
            float2 p0, p1;
            p0.x = fmaf(acc[m][j][0], i0, be0);
            p0.y = fmaf(acc[m][j][1], i0, be0);
            p1.x = fmaf(acc[m][j][2], i1, be1);
            p1.y = fmaf(acc[m][j][3], i1, be1);
            *(float2*)&Ob[(size_t)r0 * L + l] = p0;
            *(float2*)&Ob[(size_t)r1 * L + l] = p1;
        }
    }
}

// ---------------- depthwise conv (k=3, pad=1) + BN on q channels ----------------
__global__ __launch_bounds__(256) void dwconv_bn_kernel(
    const float* __restrict__ qkv, const float* __restrict__ wdw,
    const float* __restrict__ gg, const float* __restrict__ bb,
    const float* __restrict__ mm, const float* __restrict__ vv,
    float* __restrict__ outq)
{
    int idx = blockIdx.x * blockDim.x + threadIdx.x;
    int l  = idx & (RES - 1);
    int ch = (idx >> 10) & (NHKD - 1);
    int b  = idx >> 18;
    const float* row = qkv + ((size_t)b * HQKV + ch) * RES;
    float x0 = (l > 0)       ? row[l - 1] : 0.0f;
    float x1 = row[l];
    float x2 = (l < RES - 1) ? row[l + 1] : 0.0f;
    float y = x0 * wdw[ch * 3] + x1 * wdw[ch * 3 + 1] + x2 * wdw[ch * 3 + 2];
    float inv = gg[ch] * rsqrtf(vv[ch] + 1e-5f);
    outq[idx] = (y - mm[ch]) * inv + bb[ch];
}

// ---------------- fused attention: tf32 mma + cp.async pipelines ----------------
// 512 threads (16 warps); block = (b, h, 32-row n tile).
#define NT 32
#define Q_OFF    0                        // q_s[n][36] (tf32)
#define BIAS_OFF 1152
#define DSUM_OFF 2176
#define STG_OFF  2208                     // k: 2x[32][136]=8704 ; v: 2x[128][68]=17408
#define S_OFF    (STG_OFF + 17408)        // s_s[32][1028]
#define ATTN_SMEM_FLOATS (S_OFF + 32 * 1028)
#define ATTN_SMEM_BYTES  (ATTN_SMEM_FLOATS * 4)
#define KBUF 4352                         // 32*136
#define VBUF 8704                         // 128*68

__global__ __launch_bounds__(512, 1) void attn_kernel(
    const float* __restrict__ qbuf, const float* __restrict__ qkv,
    const float* __restrict__ bias, float* __restrict__ outp)
{
    extern __shared__ __align__(16) float sh[];
    float* q_s    = sh + Q_OFF;
    float* bias_s = sh + BIAS_OFF;
    float* dsum   = sh + DSUM_OFF;
    float* stg    = sh + STG_OFF;
    float* s_s    = sh + S_OFF;
    const unsigned stg_u32 = (unsigned)__cvta_generic_to_shared(stg);

    const int b = blockIdx.z, h = blockIdx.y;
    const int n0 = blockIdx.x * NT;
    const int t = threadIdx.x;
    const int lane = t & 31, wrp = t >> 5;
    const int grp = lane >> 2, tig = lane & 3;

    const float* qb = qbuf + ((size_t)b * NHKD + h * KD) * RES;
    const float* kb = qkv + ((size_t)b * HQKV + NHKD + h * KD) * RES;
    const float* vb = qkv + ((size_t)b * HQKV + 2 * NHKD + h * DV) * RES;
    const float* ab = bias + h * RES;

    auto stage_k = [&](int ch, int bf) {
        #pragma unroll
        for (int r = 0; r < 2; r++) {
            int idx = t + r * 512;
            int d = idx >> 5, m4 = (idx & 31) * 4;
            unsigned dst = stg_u32 + (unsigned)(bf * KBUF + d * 136 + m4) * 4u;
            CP16(dst, kb + (size_t)d * RES + ch * 128 + m4);
        }
    };
    auto stage_v = [&](int ch, int bf) {
        #pragma unroll
        for (int r = 0; r < 4; r++) {
            int idx = t + r * 512;
            int d = idx >> 4, m4 = (idx & 15) * 4;
            unsigned dst = stg_u32 + (unsigned)(bf * VBUF + d * 68 + m4) * 4u;
            CP16(dst, vb + (size_t)d * RES + ch * 64 + m4);
        }
    };

    stage_k(0, 0);
    CP_COMMIT();

    for (int i = t; i < 1024; i += 512) {
        int d = i >> 5, nn = i & 31;
        q_s[nn * 36 + d] = f2tf(qb[d * RES + n0 + nn]);
        bias_s[i] = ab[i];
    }
    __syncthreads();

    // ---- phase 2: S = scale*(q k) + bias via mma, 8 chunks of 128 m ----
    {
        const int nhalf = wrp & 1;
        const int msub  = wrp >> 1;
        const int nrow0 = nhalf * 16 + grp;
        const int ngA = n0 + nrow0, ngB = ngA + 8;

        float aq[4][4];
        #pragma unroll
        for (int kk = 0; kk < 4; kk++) {
            aq[kk][0] = q_s[nrow0 * 36 + kk * 8 + tig];
            aq[kk][1] = q_s[(nrow0 + 8) * 36 + kk * 8 + tig];
            aq[kk][2] = q_s[nrow0 * 36 + kk * 8 + tig + 4];
            aq[kk][3] = q_s[(nrow0 + 8) * 36 + kk * 8 + tig + 4];
        }

        for (int ch = 0; ch < 8; ch++) {
            CP_WAIT0();
            __syncthreads();
            if (ch < 7) { stage_k(ch + 1, (ch + 1) & 1); CP_COMMIT(); }
            const float* ks = stg + (ch & 1) * KBUF;

            float acc2[2][4];
            #pragma unroll
            for (int j = 0; j < 2; j++)
                #pragma unroll
                for (int r = 0; r < 4; r++) acc2[j][r] = 0.0f;

            #pragma unroll
            for (int kk = 0; kk < 4; kk++) {
                #pragma unroll
                for (int j = 0; j < 2; j++) {
                    const int mc = msub * 16 + j * 8 + grp;
                    float b0 = ks[(kk * 8 + tig) * 136 + mc];
                    float b1 = ks[(kk * 8 + tig + 4) * 136 + mc];
                    mma_tf32(acc2[j], aq[kk], b0, b1);
                }
            }
            #pragma unroll
            for (int j = 0; j < 2; j++) {
                const int mg = ch * 128 + msub * 16 + j * 8 + tig * 2;
                float2 p0, p1;
                p0.x = fmaf(acc2[j][0], ATT_SCALE, bias_s[abs(ngA - mg)]);
                p0.y = fmaf(acc2[j][1], ATT_SCALE, bias_s[abs(ngA - mg - 1)]);
                p1.x = fmaf(acc2[j][2], ATT_SCALE, bias_s[abs(ngB - mg)]);
                p1.y = fmaf(acc2[j][3], ATT_SCALE, bias_s[abs(ngB - mg - 1)]);
                *(float2*)&s_s[nrow0 * 1028 + mg]       = p0;
                *(float2*)&s_s[(nrow0 + 8) * 1028 + mg] = p1;
            }
        }
    }
    __syncthreads();           // s_s complete before softmax

    stage_v(0, 0);
    CP_COMMIT();

    // ---- phase 3: softmax per row (16 warps x 2 rows) ----
    #pragma unroll
    for (int rr = 0; rr < 2; rr++) {
        int r = wrp * 2 + rr;
        float* row = s_s + r * 1028;
        float mx = -1e30f;
        for (int i = lane * 4; i < RES; i += 128) {
            float4 x = *(const float4*)&row[i];
            mx = fmaxf(mx, fmaxf(fmaxf(x.x, x.y), fmaxf(x.z, x.w)));
        }
        #pragma unroll
        for (int o = 16; o; o >>= 1) mx = fmaxf(mx, __shfl_xor_sync(0xffffffffu, mx, o));
        float sum = 0.0f;
        for (int i = lane * 4; i < RES; i += 128) {
            float4 x = *(const float4*)&row[i];
            x.x = __expf(x.x - mx); x.y = __expf(x.y - mx);
            x.z = __expf(x.z - mx); x.w = __expf(x.w - mx);
            sum += (x.x + x.y) + (x.z + x.w);
            *(float4*)&row[i] = x;
        }
        #pragma unroll
        for (int o = 16; o; o >>= 1) sum += __shfl_xor_sync(0xffffffffu, sum, o);
        if (lane == 0) dsum[r] = 1.0f / sum;
    }
    __syncthreads();           // softmax rows + dsum ready

    // ---- phase 4: out[d][n] = sum_m v[d][m] p[n][m] via mma ----
    {
        const int dt = wrp & 3;
        const int ksp = wrp >> 2;
        float c4[2][4][4];
        #pragma unroll
        for (int su = 0; su < 2; su++)
            #pragma unroll
            for (int j = 0; j < 4; j++)
                #pragma unroll
                for (int r = 0; r < 4; r++) c4[su][j][r] = 0.0f;

        for (int ch = 0; ch < 16; ch++) {
            CP_WAIT0();
            __syncthreads();
            if (ch < 15) { stage_v(ch + 1, (ch + 1) & 1); CP_COMMIT(); }
            const float* vs = stg + (ch & 1) * VBUF;
            const int mbase = ch * 64;

            #pragma unroll
            for (int kk = 0; kk < 2; kk++) {
                const int k8 = ksp * 16 + kk * 8;
                float av[2][4];
                #pragma unroll
                for (int su = 0; su < 2; su++) {
                    const int dr = dt * 32 + su * 16 + grp;
                    av[su][0] = vs[dr * 68 + k8 + tig];
                    av[su][1] = vs[(dr + 8) * 68 + k8 + tig];
                    av[su][2] = vs[dr * 68 + k8 + tig + 4];
                    av[su][3] = vs[(dr + 8) * 68 + k8 + tig + 4];
                }
                #pragma unroll
                for (int j = 0; j < 4; j++) {
                    const int nrow = j * 8 + grp;
                    float b0 = s_s[nrow * 1028 + mbase + k8 + tig];
                    float b1 = s_s[nrow * 1028 + mbase + k8 + tig + 4];
                    mma_tf32(c4[0][j], av[0], b0, b1);
                    mma_tf32(c4[1][j], av[1], b0, b1);
                }
            }
        }
        __syncthreads();       // all warps done reading vs before red reuse

        float* red = stg;
        #pragma unroll
        for (int su = 0; su < 2; su++) {
            #pragma unroll
            for (int j = 0; j < 4; j++) {
                const int d = dt * 32 + su * 16 + grp;
                const int n = j * 8 + tig * 2;
                *(float2*)&red[ksp * 4352 + d * 34 + n] =
                    make_float2(c4[su][j][0], c4[su][j][1]);
                *(float2*)&red[ksp * 4352 + (d + 8) * 34 + n] =
                    make_float2(c4[su][j][2], c4[su][j][3]);
            }
        }
        __syncthreads();

        const int d  = t >> 2;
        const int nq = (t & 3) * 8;
        float s[8];
        #pragma unroll
        for (int i = 0; i < 8; i++) s[i] = 0.0f;
        #pragma unroll
        for (int kspl = 0; kspl < 4; kspl++) {
            const float* rp = &red[kspl * 4352 + d * 34 + nq];
            #pragma unroll
            for (int i = 0; i < 4; i++) {
                float2 v = *(const float2*)&rp[i * 2];
                s[i * 2]     += v.x;
                s[i * 2 + 1] += v.y;
            }
        }
        float4 w0, w1;
        w0.x = fmaxf(s[0] * dsum[nq + 0], 0.0f);
        w0.y = fmaxf(s[1] * dsum[nq + 1], 0.0f);
        w0.z = fmaxf(s[2] * dsum[nq + 2], 0.0f);
        w0.w = fmaxf(s[3] * dsum[nq + 3], 0.0f);
        w1.x = fmaxf(s[4] * dsum[nq + 4], 0.0f);
        w1.y = fmaxf(s[5] * dsum[nq + 5], 0.0f);
        w1.z = fmaxf(s[6] * dsum[nq + 6], 0.0f);
        w1.w = fmaxf(s[7] * dsum[nq + 7], 0.0f);
        float* ob = outp + ((size_t)b * DHDIM + h * DV) * RES + n0;
        *(float4*)&ob[(size_t)d * RES + nq]     = w0;
        *(float4*)&ob[(size_t)d * RES + nq + 4] = w1;
    }
}

// --------------------------------- launch -------------------------------------
extern "C" void kernel_launch(void* const* d_in, const int* in_sizes, int n_in,
                              void* d_out, int out_size)
{
    const float* x      = (const float*)d_in[0];
    const float* w_qkv  = (const float*)d_in[1];
    const float* qkv_g  = (const float*)d_in[2];
    const float* qkv_b  = (const float*)d_in[3];
    const float* qkv_m  = (const float*)d_in[4];
    const float* qkv_v  = (const float*)d_in[5];
    const float* w_dw   = (const float*)d_in[6];
    const float* dw_g   = (const float*)d_in[7];
    const float* dw_b   = (const float*)d_in[8];
    const float* dw_m   = (const float*)d_in[9];
    const float* dw_v   = (const float*)d_in[10];
    const float* w_proj = (const float*)d_in[11];
    const float* proj_g = (const float*)d_in[12];
    const float* proj_b = (const float*)d_in[13];
    const float* proj_m = (const float*)d_in[14];
    const float* proj_v = (const float*)d_in[15];
    const float* att_bias = (const float*)d_in[16];

    float *p_qkv, *p_q, *p_att;
    cudaGetSymbolAddress((void**)&p_qkv, g_qkv);
    cudaGetSymbolAddress((void**)&p_q,   g_q);
    cudaGetSymbolAddress((void**)&p_att, g_att);

    cudaFuncSetAttribute(gemm_tf32_bn, cudaFuncAttributeMaxDynamicSharedMemorySize,
                         GEMM_SMEM_BYTES);
    cudaFuncSetAttribute(attn_kernel, cudaFuncAttributeMaxDynamicSharedMemorySize,
                         ATTN_SMEM_BYTES);

    gemm_tf32_bn<<<dim3(RES / 128, HQKV / 128, BATCH), 256, GEMM_SMEM_BYTES>>>(
        w_qkv, x, qkv_g, qkv_b, qkv_m, qkv_v, p_qkv, HQKV, DIMC, RES);

    dwconv_bn_kernel<<<(BATCH * NHKD * RES) / 256, 256>>>(
        p_qkv, w_dw, dw_g, dw_b, dw_m, dw_v, p_q);

    attn_kernel<<<dim3(RES / NT, NHEAD, BATCH), 512, ATTN_SMEM_BYTES>>>(
        p_q, p_qkv, att_bias, p_att);

    gemm_tf32_bn<<<dim3(RES / 128, DIMC / 128, BATCH), 256, GEMM_SMEM_BYTES>>>(
        w_proj, p_att, proj_g, proj_b, proj_m, proj_v, (float*)d_out,
        DIMC, DHDIM, RES);
}

// round 11
// speedup vs baseline: 1.3855x; 1.3855x over previous
#include <cuda_runtime.h>
#include <math.h>

#define BATCH 16
#define DIMC  512
#define RES   1024
#define NHKD  256
#define HQKV  1536
#define DHDIM 1024
#define NHEAD 8
#define KD    32
#define DV    128
#define ATT_SCALE 0.17677669529663687f

// ---------------- scratch (static device globals; no allocations) -------------
__device__ float g_qkv[BATCH * HQKV * RES];
__device__ float g_q  [BATCH * NHKD * RES];
__device__ float g_att[BATCH * DHDIM * RES];

// ---------------- tf32 / cp.async helpers --------------------------------------
__device__ __forceinline__ float f2tf(float x) {
    unsigned r;
    asm("cvt.rna.tf32.f32 %0, %1;" : "=r"(r) : "f"(x));
    return __uint_as_float(r);
}
__device__ __forceinline__ void mma_tf32(float c[4], const float a[4],
                                         float b0, float b1) {
    asm volatile(
        "mma.sync.aligned.m16n8k8.row.col.f32.tf32.tf32.f32 "
        "{%0,%1,%2,%3}, {%4,%5,%6,%7}, {%8,%9}, {%0,%1,%2,%3};"
        : "+f"(c[0]), "+f"(c[1]), "+f"(c[2]), "+f"(c[3])
        : "r"(__float_as_uint(a[0])), "r"(__float_as_uint(a[1])),
          "r"(__float_as_uint(a[2])), "r"(__float_as_uint(a[3])),
          "r"(__float_as_uint(b0)), "r"(__float_as_uint(b1)));
}
#define CP16(dst, src) \
    asm volatile("cp.async.cg.shared.global [%0], [%1], 16;" :: "r"(dst), "l"(src))
#define CP_COMMIT() asm volatile("cp.async.commit_group;")
#define CP_WAIT0()  asm volatile("cp.async.wait_group 0;")
#define CP_WAIT1()  asm volatile("cp.async.wait_group 1;")
#define CP_WAIT2()  asm volatile("cp.async.wait_group 2;")

// ---------------- GEMM (C[b,o,l] = sum_c W[o,c] * X[b,c,l]) + BN ---------------
// tf32 mma, 128x128 tile, K-chunk 16, 256 threads, 4-stage cp.async pipeline.
#define GSTG_A 2560
#define GSTG_B 2176
#define GSTG   (GSTG_A + GSTG_B)
#define GEMM_SMEM_BYTES (4 * GSTG * 4)

__global__ __launch_bounds__(256) void gemm_tf32_bn(
    const float* __restrict__ W, const float* __restrict__ X,
    const float* __restrict__ gg, const float* __restrict__ bb,
    const float* __restrict__ mm, const float* __restrict__ vv,
    float* __restrict__ out, int O, int C, int L)
{
    extern __shared__ __align__(16) float gsh[];
    const unsigned sh_u32 = (unsigned)__cvta_generic_to_shared(gsh);

    const int b  = blockIdx.z;
    const float* Xb = X + (size_t)b * C * L;
    float* Ob = out + (size_t)b * O * L;
    const int o0 = blockIdx.y * 128;
    const int l0 = blockIdx.x * 128;
    const int t = threadIdx.x, lane = t & 31, wid = t >> 5;
    const int wm = wid & 3, wn = wid >> 2;
    const int tig = lane & 3, grp = lane >> 2;

    float acc[2][8][4];
    #pragma unroll
    for (int m = 0; m < 2; m++)
        #pragma unroll
        for (int j = 0; j < 8; j++)
            #pragma unroll
            for (int r = 0; r < 4; r++) acc[m][j][r] = 0.0f;

    auto stage = [&](int k0, int s) {
        unsigned base = sh_u32 + (unsigned)(s * GSTG) * 4u;
        #pragma unroll
        for (int r = 0; r < 2; r++) {
            int idx = t + r * 256;
            int row = idx >> 2, kq = (idx & 3) * 4;
            CP16(base + (unsigned)(row * 20 + kq) * 4u,
                 &W[(size_t)(o0 + row) * C + k0 + kq]);
        }
        #pragma unroll
        for (int r = 0; r < 2; r++) {
            int idx = t + r * 256;
            int k = idx >> 5, m4 = (idx & 31) * 4;
            CP16(base + (unsigned)(GSTG_A + k * 136 + m4) * 4u,
                 &Xb[(size_t)(k0 + k) * L + l0 + m4]);
        }
    };

    const int niter = C / 16;
    stage(0, 0);  CP_COMMIT();
    stage(16, 1); CP_COMMIT();
    stage(32, 2); CP_COMMIT();

    for (int it = 0; it < niter; it++) {
        const int inflight = niter - it;
        if (inflight >= 3)      { CP_WAIT2(); }
        else if (inflight == 2) { CP_WAIT1(); }
        else                    { CP_WAIT0(); }
        __syncthreads();
        if (it + 3 < niter) { stage((it + 3) * 16, (it + 3) & 3); CP_COMMIT(); }

        const float* As = gsh + (it & 3) * GSTG;
        const float* Bs = As + GSTG_A;

        #pragma unroll
        for (int kk = 0; kk < 2; kk++) {
            float a[2][4];
            #pragma unroll
            for (int m = 0; m < 2; m++) {
                const int row = wm * 32 + m * 16 + grp;
                a[m][0] = As[row * 20 + kk * 8 + tig];
                a[m][1] = As[(row + 8) * 20 + kk * 8 + tig];
                a[m][2] = As[row * 20 + kk * 8 + tig + 4];
                a[m][3] = As[(row + 8) * 20 + kk * 8 + tig + 4];
            }
            #pragma unroll
            for (int j = 0; j < 8; j++) {
                const int col = wn * 64 + j * 8 + grp;
                float b0 = Bs[(kk * 8 + tig) * 136 + col];
                float b1 = Bs[(kk * 8 + tig + 4) * 136 + col];
                mma_tf32(acc[0][j], a[0], b0, b1);
                mma_tf32(acc[1][j], a[1], b0, b1);
            }
        }
    }

    #pragma unroll
    for (int m = 0; m < 2; m++) {
        const int r0 = o0 + wm * 32 + m * 16 + grp;
        const int r1 = r0 + 8;
        const float i0 = gg[r0] * rsqrtf(vv[r0] + 1e-5f);
        const float be0 = bb[r0] - mm[r0] * i0;
        const float i1 = gg[r1] * rsqrtf(vv[r1] + 1e-5f);
        const float be1 = bb[r1] - mm[r1] * i1;
        #pragma unroll
        for (int j = 0; j < 8; j++) {
            const int l = l0 + wn * 64 + j * 8 + tig * 2;
            float2 p0, p1;
            p0.x = fmaf(acc[m][j][0], i0, be0);
            p0.y = fmaf(acc[m][j][1], i0, be0);
            p1.x = fmaf(acc[m][j][2], i1, be1);
            p1.y = fmaf(acc[m][j][3], i1, be1);
            *(float2*)&Ob[(size_t)r0 * L + l] = p0;
            *(float2*)&Ob[(size_t)r1 * L + l] = p1;
        }
    }
}

// ---------------- depthwise conv (k=3, pad=1) + BN on q channels ----------------
__global__ __launch_bounds__(256) void dwconv_bn_kernel(
    const float* __restrict__ qkv, const float* __restrict__ wdw,
    const float* __restrict__ gg, const float* __restrict__ bb,
    const float* __restrict__ mm, const float* __restrict__ vv,
    float* __restrict__ outq)
{
    int idx = blockIdx.x * blockDim.x + threadIdx.x;
    int l  = idx & (RES - 1);
    int ch = (idx >> 10) & (NHKD - 1);
    int b  = idx >> 18;
    const float* row = qkv + ((size_t)b * HQKV + ch) * RES;
    float x0 = (l > 0)       ? row[l - 1] : 0.0f;
    float x1 = row[l];
    float x2 = (l < RES - 1) ? row[l + 1] : 0.0f;
    float y = x0 * wdw[ch * 3] + x1 * wdw[ch * 3 + 1] + x2 * wdw[ch * 3 + 2];
    float inv = gg[ch] * rsqrtf(vv[ch] + 1e-5f);
    outq[idx] = (y - mm[ch]) * inv + bb[ch];
}

// ---------------- flash attention: online softmax, 128 q rows per block --------
// 512 threads (16 warps). Warp w<8: n-tile w*16, m-half 0, d-half 0.
//                          Warp w>=8: n-tile (w-8)*16, m-half 1, d-half 1.
// smem floats:
#define FQ_OFF    0                     // q_s[128][36]
#define FB_OFF    4608                  // bias[1024]
#define FPM_OFF   5632                  // pmax[2][128]
#define FPS_OFF   5888                  // psum[2][128]
#define FDI_OFF   6144                  // dinv[128]
#define FKV_OFF   6272                  // k: 2x32*72=4608 ; v: 2x128*68=17408
#define FK_BUF    2304
#define FV_OFF    (FKV_OFF + 4608)      // 10880
#define FV_BUF    8704
#define FP_OFF    (FV_OFF + 17408)      // 28288: P[128][68]
#define FLASH_FLOATS (FP_OFF + 8704)    // 36992
#define FLASH_SMEM_BYTES (FLASH_FLOATS * 4)
#define FOSM_OFF  FKV_OFF               // epilogue O[128][129] = 16512 (reuses k/v/P)

__global__ __launch_bounds__(512, 1) void flash_attn_kernel(
    const float* __restrict__ qbuf, const float* __restrict__ qkv,
    const float* __restrict__ bias, float* __restrict__ outp)
{
    extern __shared__ __align__(16) float sh[];
    float* q_s    = sh + FQ_OFF;
    float* bias_s = sh + FB_OFF;
    float* pmax   = sh + FPM_OFF;
    float* psum   = sh + FPS_OFF;
    float* dinv   = sh + FDI_OFF;
    float* kbuf   = sh + FKV_OFF;
    float* vbuf   = sh + FV_OFF;
    float* Pbuf   = sh + FP_OFF;
    const unsigned sh_u32 = (unsigned)__cvta_generic_to_shared(sh);

    const int b = blockIdx.z, h = blockIdx.y;
    const int n0 = blockIdx.x * 128;
    const int t = threadIdx.x;
    const int lane = t & 31, wid = t >> 5;
    const int grp = lane >> 2, tig = lane & 3;
    const int mh = wid >> 3;            // m-half & d-half
    const int nt = (wid & 7) * 16;      // local n-tile base
    const int rowA = nt + grp, rowB = rowA + 8;
    const int ngA = n0 + rowA, ngB = n0 + rowB;

    const float* qb = qbuf + ((size_t)b * NHKD + h * KD) * RES;
    const float* kb = qkv + ((size_t)b * HQKV + NHKD + h * KD) * RES;
    const float* vb = qkv + ((size_t)b * HQKV + 2 * NHKD + h * DV) * RES;
    const float* ab = bias + h * RES;

    // stage k chunk [32 d][64 m] + v chunk [128 d][64 m]
    auto stage_kv = [&](int ch, int bf) {
        {
            int d = t >> 4, m4 = (t & 15) * 4;
            CP16(sh_u32 + (unsigned)(FKV_OFF + bf * FK_BUF + d * 72 + m4) * 4u,
                 kb + (size_t)d * RES + ch * 64 + m4);
        }
        #pragma unroll
        for (int r = 0; r < 4; r++) {
            int idx = t + r * 512;
            int d = idx >> 4, m4 = (idx & 15) * 4;
            CP16(sh_u32 + (unsigned)(FV_OFF + bf * FV_BUF + d * 68 + m4) * 4u,
                 vb + (size_t)d * RES + ch * 64 + m4);
        }
    };

    stage_kv(0, 0);
    CP_COMMIT();

    // q tile (tf32, n-major) + bias row
    for (int i = t; i < 4096; i += 512) {
        int d = i >> 7, nn = i & 127;
        q_s[nn * 36 + d] = f2tf(qb[(size_t)d * RES + n0 + nn]);
    }
    for (int i = t; i < 1024; i += 512) bias_s[i] = ab[i];
    __syncthreads();

    // preload q A-fragments (rows rowA/rowB, K = 32 d)
    float aq[4][4];
    #pragma unroll
    for (int kk = 0; kk < 4; kk++) {
        aq[kk][0] = q_s[rowA * 36 + kk * 8 + tig];
        aq[kk][1] = q_s[rowB * 36 + kk * 8 + tig];
        aq[kk][2] = q_s[rowA * 36 + kk * 8 + tig + 4];
        aq[kk][3] = q_s[rowB * 36 + kk * 8 + tig + 4];
    }

    float o[8][4];
    #pragma unroll
    for (int j = 0; j < 8; j++)
        #pragma unroll
        for (int r = 0; r < 4; r++) o[j][r] = 0.0f;
    float rmaxA = -1e30f, rmaxB = -1e30f;
    float rsumA = 0.0f,  rsumB = 0.0f;

    for (int ch = 0; ch < 16; ch++) {
        CP_WAIT0();
        __syncthreads();                       // chunk staged; Pbuf free
        if (ch < 15) { stage_kv(ch + 1, (ch + 1) & 1); CP_COMMIT(); }
        const float* ks = kbuf + (ch & 1) * FK_BUF;
        const float* vs = vbuf + (ch & 1) * FV_BUF;

        // ---- S = q.k^T for this warp's [16 n][32 m] ----
        float s[4][4];
        #pragma unroll
        for (int mt = 0; mt < 4; mt++)
            #pragma unroll
            for (int r = 0; r < 4; r++) s[mt][r] = 0.0f;
        #pragma unroll
        for (int kk = 0; kk < 4; kk++) {
            #pragma unroll
            for (int mt = 0; mt < 4; mt++) {
                const int mc = mh * 32 + mt * 8 + grp;
                float b0 = ks[(kk * 8 + tig) * 72 + mc];
                float b1 = ks[(kk * 8 + tig + 4) * 72 + mc];
                mma_tf32(s[mt], aq[kk], b0, b1);
            }
        }
        // scale + bias
        #pragma unroll
        for (int mt = 0; mt < 4; mt++) {
            const int mg = ch * 64 + mh * 32 + mt * 8 + 2 * tig;
            s[mt][0] = fmaf(s[mt][0], ATT_SCALE, bias_s[abs(ngA - mg)]);
            s[mt][1] = fmaf(s[mt][1], ATT_SCALE, bias_s[abs(ngA - mg - 1)]);
            s[mt][2] = fmaf(s[mt][2], ATT_SCALE, bias_s[abs(ngB - mg)]);
            s[mt][3] = fmaf(s[mt][3], ATT_SCALE, bias_s[abs(ngB - mg - 1)]);
        }
        // partial row max over this m-half
        float mA = -1e30f, mB = -1e30f;
        #pragma unroll
        for (int mt = 0; mt < 4; mt++) {
            mA = fmaxf(mA, fmaxf(s[mt][0], s[mt][1]));
            mB = fmaxf(mB, fmaxf(s[mt][2], s[mt][3]));
        }
        mA = fmaxf(mA, __shfl_xor_sync(0xffffffffu, mA, 1));
        mA = fmaxf(mA, __shfl_xor_sync(0xffffffffu, mA, 2));
        mB = fmaxf(mB, __shfl_xor_sync(0xffffffffu, mB, 1));
        mB = fmaxf(mB, __shfl_xor_sync(0xffffffffu, mB, 2));
        if (tig == 0) { pmax[mh * 128 + rowA] = mA; pmax[mh * 128 + rowB] = mB; }
        __syncthreads();

        // new running max + rescale factor
        float mnA = fmaxf(rmaxA, fmaxf(pmax[rowA], pmax[128 + rowA]));
        float mnB = fmaxf(rmaxB, fmaxf(pmax[rowB], pmax[128 + rowB]));
        float fA = __expf(rmaxA - mnA); rmaxA = mnA;
        float fB = __expf(rmaxB - mnB); rmaxB = mnB;

        // exp, partial sums, write P
        float sA = 0.0f, sB = 0.0f;
        #pragma unroll
        for (int mt = 0; mt < 4; mt++) {
            s[mt][0] = __expf(s[mt][0] - mnA);
            s[mt][1] = __expf(s[mt][1] - mnA);
            s[mt][2] = __expf(s[mt][2] - mnB);
            s[mt][3] = __expf(s[mt][3] - mnB);
            sA += s[mt][0] + s[mt][1];
            sB += s[mt][2] + s[mt][3];
            const int mc = mh * 32 + mt * 8 + 2 * tig;
            *(float2*)&Pbuf[rowA * 68 + mc] = make_float2(s[mt][0], s[mt][1]);
            *(float2*)&Pbuf[rowB * 68 + mc] = make_float2(s[mt][2], s[mt][3]);
        }
        sA += __shfl_xor_sync(0xffffffffu, sA, 1);
        sA += __shfl_xor_sync(0xffffffffu, sA, 2);
        sB += __shfl_xor_sync(0xffffffffu, sB, 1);
        sB += __shfl_xor_sync(0xffffffffu, sB, 2);
        if (tig == 0) { psum[mh * 128 + rowA] = sA; psum[mh * 128 + rowB] = sB; }

        // rescale O accumulators
        #pragma unroll
        for (int j = 0; j < 8; j++) {
            o[j][0] *= fA; o[j][1] *= fA;
            o[j][2] *= fB; o[j][3] *= fB;
        }
        __syncthreads();                      // P + psum visible

        rsumA = rsumA * fA + psum[rowA] + psum[128 + rowA];
        rsumB = rsumB * fB + psum[rowB] + psum[128 + rowB];

        // ---- O += P.V^T : warp's [16 n][64 d] over K = 64 m ----
        const int d0 = mh * 64;
        #pragma unroll
        for (int kk = 0; kk < 8; kk++) {
            float a[4];
            a[0] = Pbuf[rowA * 68 + kk * 8 + tig];
            a[1] = Pbuf[rowB * 68 + kk * 8 + tig];
            a[2] = Pbuf[rowA * 68 + kk * 8 + tig + 4];
            a[3] = Pbuf[rowB * 68 + kk * 8 + tig + 4];
            #pragma unroll
            for (int j = 0; j < 8; j++) {
                const int dc = d0 + j * 8 + grp;
                float b0 = vs[dc * 68 + kk * 8 + tig];
                float b1 = vs[dc * 68 + kk * 8 + tig + 4];
                mma_tf32(o[j], a, b0, b1);
            }
        }
    }

    // ---- epilogue: 1/sum, transpose via smem, relu, store out[d][n] ----
    if (mh == 0 && tig == 0) {
        dinv[rowA] = 1.0f / rsumA;
        dinv[rowB] = 1.0f / rsumB;
    }
    __syncthreads();                          // last PV reads done; reuse stg
    float* Osm = sh + FOSM_OFF;               // [128 n][stride 129]
    {
        const int d0 = mh * 64;
        #pragma unroll
        for (int j = 0; j < 8; j++) {
            const int dc = d0 + j * 8 + 2 * tig;
            Osm[rowA * 129 + dc]     = o[j][0];
            Osm[rowA * 129 + dc + 1] = o[j][1];
            Osm[rowB * 129 + dc]     = o[j][2];
            Osm[rowB * 129 + dc + 1] = o[j][3];
        }
    }
    __syncthreads();
    {
        const int d  = t >> 2;
        const int ns = (t & 3) * 32;
        float* ob = outp + ((size_t)b * DHDIM + h * DV + d) * RES + n0;
        #pragma unroll
        for (int i = 0; i < 8; i++) {
            const int n = ns + i * 4;
            float4 w;
            w.x = fmaxf(Osm[(n + 0) * 129 + d] * dinv[n + 0], 0.0f);
            w.y = fmaxf(Osm[(n + 1) * 129 + d] * dinv[n + 1], 0.0f);
            w.z = fmaxf(Osm[(n + 2) * 129 + d] * dinv[n + 2], 0.0f);
            w.w = fmaxf(Osm[(n + 3) * 129 + d] * dinv[n + 3], 0.0f);
            *(float4*)&ob[n] = w;
        }
    }
}

// --------------------------------- launch -------------------------------------
extern "C" void kernel_launch(void* const* d_in, const int* in_sizes, int n_in,
                              void* d_out, int out_size)
{
    const float* x      = (const float*)d_in[0];
    const float* w_qkv  = (const float*)d_in[1];
    const float* qkv_g  = (const float*)d_in[2];
    const float* qkv_b  = (const float*)d_in[3];
    const float* qkv_m  = (const float*)d_in[4];
    const float* qkv_v  = (const float*)d_in[5];
    const float* w_dw   = (const float*)d_in[6];
    const float* dw_g   = (const float*)d_in[7];
    const float* dw_b   = (const float*)d_in[8];
    const float* dw_m   = (const float*)d_in[9];
    const float* dw_v   = (const float*)d_in[10];
    const float* w_proj = (const float*)d_in[11];
    const float* proj_g = (const float*)d_in[12];
    const float* proj_b = (const float*)d_in[13];
    const float* proj_m = (const float*)d_in[14];
    const float* proj_v = (const float*)d_in[15];
    const float* att_bias = (const float*)d_in[16];

    float *p_qkv, *p_q, *p_att;
    cudaGetSymbolAddress((void**)&p_qkv, g_qkv);
    cudaGetSymbolAddress((void**)&p_q,   g_q);
    cudaGetSymbolAddress((void**)&p_att, g_att);

    cudaFuncSetAttribute(gemm_tf32_bn, cudaFuncAttributeMaxDynamicSharedMemorySize,
                         GEMM_SMEM_BYTES);
    cudaFuncSetAttribute(flash_attn_kernel, cudaFuncAttributeMaxDynamicSharedMemorySize,
                         FLASH_SMEM_BYTES);

    gemm_tf32_bn<<<dim3(RES / 128, HQKV / 128, BATCH), 256, GEMM_SMEM_BYTES>>>(
        w_qkv, x, qkv_g, qkv_b, qkv_m, qkv_v, p_qkv, HQKV, DIMC, RES);

    dwconv_bn_kernel<<<(BATCH * NHKD * RES) / 256, 256>>>(
        p_qkv, w_dw, dw_g, dw_b, dw_m, dw_v, p_q);

    flash_attn_kernel<<<dim3(RES / 128, NHEAD, BATCH), 512, FLASH_SMEM_BYTES>>>(
        p_q, p_qkv, att_bias, p_att);

    gemm_tf32_bn<<<dim3(RES / 128, DIMC / 128, BATCH), 256, GEMM_SMEM_BYTES>>>(
        w_proj, p_att, proj_g, proj_b, proj_m, proj_v, (float*)d_out,
        DIMC, DHDIM, RES);
}

// round 12
// speedup vs baseline: 1.3865x; 1.0007x over previous
#include <cuda_runtime.h>
#include <math.h>

#define BATCH 16
#define DIMC  512
#define RES   1024
#define NHKD  256
#define HQKV  1536
#define DHDIM 1024
#define NHEAD 8
#define KD    32
#define DV    128
#define ATT_SCALE 0.17677669529663687f

// ---------------- scratch (static device globals; no allocations) -------------
__device__ float g_qkv[BATCH * HQKV * RES];
__device__ float g_q  [BATCH * NHKD * RES];
__device__ float g_att[BATCH * DHDIM * RES];

// ---------------- tf32 / cp.async helpers --------------------------------------
__device__ __forceinline__ float f2tf(float x) {
    unsigned r;
    asm("cvt.rna.tf32.f32 %0, %1;" : "=r"(r) : "f"(x));
    return __uint_as_float(r);
}
__device__ __forceinline__ void mma_tf32(float c[4], const float a[4],
                                         float b0, float b1) {
    asm volatile(
        "mma.sync.aligned.m16n8k8.row.col.f32.tf32.tf32.f32 "
        "{%0,%1,%2,%3}, {%4,%5,%6,%7}, {%8,%9}, {%0,%1,%2,%3};"
        : "+f"(c[0]), "+f"(c[1]), "+f"(c[2]), "+f"(c[3])
        : "r"(__float_as_uint(a[0])), "r"(__float_as_uint(a[1])),
          "r"(__float_as_uint(a[2])), "r"(__float_as_uint(a[3])),
          "r"(__float_as_uint(b0)), "r"(__float_as_uint(b1)));
}
#define CP16(dst, src) \
    asm volatile("cp.async.cg.shared.global [%0], [%1], 16;" :: "r"(dst), "l"(src))
#define CP_COMMIT() asm volatile("cp.async.commit_group;")
#define CP_WAIT0()  asm volatile("cp.async.wait_group 0;")
#define CP_WAIT1()  asm volatile("cp.async.wait_group 1;")
#define CP_WAIT2()  asm volatile("cp.async.wait_group 2;")

// ---------------- GEMM (C[b,o,l] = sum_c W[o,c] * X[b,c,l]) + BN ---------------
// tf32 mma, 128x128 tile, K-chunk 16, 256 threads, 4-stage cp.async pipeline.
#define GSTG_A 2560
#define GSTG_B 2176
#define GSTG   (GSTG_A + GSTG_B)
#define GEMM_SMEM_BYTES (4 * GSTG * 4)

__global__ __launch_bounds__(256) void gemm_tf32_bn(
    const float* __restrict__ W, const float* __restrict__ X,
    const float* __restrict__ gg, const float* __restrict__ bb,
    const float* __restrict__ mm, const float* __restrict__ vv,
    float* __restrict__ out, int O, int C, int L)
{
    extern __shared__ __align__(16) float gsh[];
    const unsigned sh_u32 = (unsigned)__cvta_generic_to_shared(gsh);

    const int b  = blockIdx.z;
    const float* Xb = X + (size_t)b * C * L;
    float* Ob = out + (size_t)b * O * L;
    const int o0 = blockIdx.y * 128;
    const int l0 = blockIdx.x * 128;
    const int t = threadIdx.x, lane = t & 31, wid = t >> 5;
    const int wm = wid & 3, wn = wid >> 2;
    const int tig = lane & 3, grp = lane >> 2;

    float acc[2][8][4];
    #pragma unroll
    for (int m = 0; m < 2; m++)
        #pragma unroll
        for (int j = 0; j < 8; j++)
            #pragma unroll
            for (int r = 0; r < 4; r++) acc[m][j][r] = 0.0f;

    auto stage = [&](int k0, int s) {
        unsigned base = sh_u32 + (unsigned)(s * GSTG) * 4u;
        #pragma unroll
        for (int r = 0; r < 2; r++) {
            int idx = t + r * 256;
            int row = idx >> 2, kq = (idx & 3) * 4;
            CP16(base + (unsigned)(row * 20 + kq) * 4u,
                 &W[(size_t)(o0 + row) * C + k0 + kq]);
        }
        #pragma unroll
        for (int r = 0; r < 2; r++) {
            int idx = t + r * 256;
            int k = idx >> 5, m4 = (idx & 31) * 4;
            CP16(base + (unsigned)(GSTG_A + k * 136 + m4) * 4u,
                 &Xb[(size_t)(k0 + k) * L + l0 + m4]);
        }
    };

    const int niter = C / 16;
    stage(0, 0);  CP_COMMIT();
    stage(16, 1); CP_COMMIT();
    stage(32, 2); CP_COMMIT();

    for (int it = 0; it < niter; it++) {
        const int inflight = niter - it;
        if (inflight >= 3)      { CP_WAIT2(); }
        else if (inflight == 2) { CP_WAIT1(); }
        else                    { CP_WAIT0(); }
        __syncthreads();
        if (it + 3 < niter) { stage((it + 3) * 16, (it + 3) & 3); CP_COMMIT(); }

        const float* As = gsh + (it & 3) * GSTG;
        const float* Bs = As + GSTG_A;

        #pragma unroll
        for (int kk = 0; kk < 2; kk++) {
            float a[2][4];
            #pragma unroll
            for (int m = 0; m < 2; m++) {
                const int row = wm * 32 + m * 16 + grp;
                a[m][0] = As[row * 20 + kk * 8 + tig];
                a[m][1] = As[(row + 8) * 20 + kk * 8 + tig];
                a[m][2] = As[row * 20 + kk * 8 + tig + 4];
                a[m][3] = As[(row + 8) * 20 + kk * 8 + tig + 4];
            }
            #pragma unroll
            for (int j = 0; j < 8; j++) {
                const int col = wn * 64 + j * 8 + grp;
                float b0 = Bs[(kk * 8 + tig) * 136 + col];
                float b1 = Bs[(kk * 8 + tig + 4) * 136 + col];
                mma_tf32(acc[0][j], a[0], b0, b1);
                mma_tf32(acc[1][j], a[1], b0, b1);
            }
        }
    }

    #pragma unroll
    for (int m = 0; m < 2; m++) {
        const int r0 = o0 + wm * 32 + m * 16 + grp;
        const int r1 = r0 + 8;
        const float i0 = gg[r0] * rsqrtf(vv[r0] + 1e-5f);
        const float be0 = bb[r0] - mm[r0] * i0;
        const float i1 = gg[r1] * rsqrtf(vv[r1] + 1e-5f);
        const float be1 = bb[r1] - mm[r1] * i1;
        #pragma unroll
        for (int j = 0; j < 8; j++) {
            const int l = l0 + wn * 64 + j * 8 + tig * 2;
            float2 p0, p1;
            p0.x = fmaf(acc[m][j][0], i0, be0);
            p0.y = fmaf(acc[m][j][1], i0, be0);
            p1.x = fmaf(acc[m][j][2], i1, be1);
            p1.y = fmaf(acc[m][j][3], i1, be1);
            *(float2*)&Ob[(size_t)r0 * L + l] = p0;
            *(float2*)&Ob[(size_t)r1 * L + l] = p1;
        }
    }
}

// ---------------- depthwise conv (k=3, pad=1) + BN on q channels ----------------
__global__ __launch_bounds__(256) void dwconv_bn_kernel(
    const float* __restrict__ qkv, const float* __restrict__ wdw,
    const float* __restrict__ gg, const float* __restrict__ bb,
    const float* __restrict__ mm, const float* __restrict__ vv,
    float* __restrict__ outq)
{
    int idx = blockIdx.x * blockDim.x + threadIdx.x;
    int l  = idx & (RES - 1);
    int ch = (idx >> 10) & (NHKD - 1);
    int b  = idx >> 18;
    const float* row = qkv + ((size_t)b * HQKV + ch) * RES;
    float x0 = (l > 0)       ? row[l - 1] : 0.0f;
    float x1 = row[l];
    float x2 = (l < RES - 1) ? row[l + 1] : 0.0f;
    float y = x0 * wdw[ch * 3] + x1 * wdw[ch * 3 + 1] + x2 * wdw[ch * 3 + 2];
    float inv = gg[ch] * rsqrtf(vv[ch] + 1e-5f);
    outq[idx] = (y - mm[ch]) * inv + bb[ch];
}

// ---------------- flash attention: online softmax, 128 q rows per block --------
// 512 threads (16 warps). Warp w<8: n-tile w*16, m-half 0, d-half 0.
//                          Warp w>=8: n-tile (w-8)*16, m-half 1, d-half 1.
// smem floats:
#define FQ_OFF    0                     // q_s[128][36]
#define FB_OFF    4608                  // bias[1024]
#define FPM_OFF   5632                  // pmax[2][128]
#define FPS_OFF   5888                  // psum[2][128]
#define FDI_OFF   6144                  // dinv[128]
#define FKV_OFF   6272                  // k: 2x32*72=4608 ; v: 2x128*68=17408
#define FK_BUF    2304
#define FV_OFF    (FKV_OFF + 4608)      // 10880
#define FV_BUF    8704
#define FP_OFF    (FV_OFF + 17408)      // 28288: P[128][68]
#define FLASH_FLOATS (FP_OFF + 8704)    // 36992
#define FLASH_SMEM_BYTES (FLASH_FLOATS * 4)
#define FOSM_OFF  FKV_OFF               // epilogue O[128][129] = 16512 (reuses k/v/P)

__global__ __launch_bounds__(512, 1) void flash_attn_kernel(
    const float* __restrict__ qbuf, const float* __restrict__ qkv,
    const float* __restrict__ bias, float* __restrict__ outp)
{
    extern __shared__ __align__(16) float sh[];
    float* q_s    = sh + FQ_OFF;
    float* bias_s = sh + FB_OFF;
    float* pmax   = sh + FPM_OFF;
    float* psum   = sh + FPS_OFF;
    float* dinv   = sh + FDI_OFF;
    float* kbuf   = sh + FKV_OFF;
    float* vbuf   = sh + FV_OFF;
    float* Pbuf   = sh + FP_OFF;
    const unsigned sh_u32 = (unsigned)__cvta_generic_to_shared(sh);

    const int b = blockIdx.z, h = blockIdx.y;
    const int n0 = blockIdx.x * 128;
    const int t = threadIdx.x;
    const int lane = t & 31, wid = t >> 5;
    const int grp = lane >> 2, tig = lane & 3;
    const int mh = wid >> 3;            // m-half & d-half
    const int nt = (wid & 7) * 16;      // local n-tile base
    const int rowA = nt + grp, rowB = rowA + 8;
    const int ngA = n0 + rowA, ngB = n0 + rowB;

    const float* qb = qbuf + ((size_t)b * NHKD + h * KD) * RES;
    const float* kb = qkv + ((size_t)b * HQKV + NHKD + h * KD) * RES;
    const float* vb = qkv + ((size_t)b * HQKV + 2 * NHKD + h * DV) * RES;
    const float* ab = bias + h * RES;

    // stage k chunk [32 d][64 m] + v chunk [128 d][64 m]
    auto stage_kv = [&](int ch, int bf) {
        {
            int d = t >> 4, m4 = (t & 15) * 4;
            CP16(sh_u32 + (unsigned)(FKV_OFF + bf * FK_BUF + d * 72 + m4) * 4u,
                 kb + (size_t)d * RES + ch * 64 + m4);
        }
        #pragma unroll
        for (int r = 0; r < 4; r++) {
            int idx = t + r * 512;
            int d = idx >> 4, m4 = (idx & 15) * 4;
            CP16(sh_u32 + (unsigned)(FV_OFF + bf * FV_BUF + d * 68 + m4) * 4u,
                 vb + (size_t)d * RES + ch * 64 + m4);
        }
    };

    stage_kv(0, 0);
    CP_COMMIT();

    // q tile (tf32, n-major) + bias row
    for (int i = t; i < 4096; i += 512) {
        int d = i >> 7, nn = i & 127;
        q_s[nn * 36 + d] = f2tf(qb[(size_t)d * RES + n0 + nn]);
    }
    for (int i = t; i < 1024; i += 512) bias_s[i] = ab[i];
    __syncthreads();

    // preload q A-fragments (rows rowA/rowB, K = 32 d)
    float aq[4][4];
    #pragma unroll
    for (int kk = 0; kk < 4; kk++) {
        aq[kk][0] = q_s[rowA * 36 + kk * 8 + tig];
        aq[kk][1] = q_s[rowB * 36 + kk * 8 + tig];
        aq[kk][2] = q_s[rowA * 36 + kk * 8 + tig + 4];
        aq[kk][3] = q_s[rowB * 36 + kk * 8 + tig + 4];
    }

    float o[8][4];
    #pragma unroll
    for (int j = 0; j < 8; j++)
        #pragma unroll
        for (int r = 0; r < 4; r++) o[j][r] = 0.0f;
    float rmaxA = -1e30f, rmaxB = -1e30f;
    float rsumA = 0.0f,  rsumB = 0.0f;

    for (int ch = 0; ch < 16; ch++) {
        CP_WAIT0();
        __syncthreads();                       // chunk staged; Pbuf free
        if (ch < 15) { stage_kv(ch + 1, (ch + 1) & 1); CP_COMMIT(); }
        const float* ks = kbuf + (ch & 1) * FK_BUF;
        const float* vs = vbuf + (ch & 1) * FV_BUF;

        // ---- S = q.k^T for this warp's [16 n][32 m] ----
        float s[4][4];
        #pragma unroll
        for (int mt = 0; mt < 4; mt++)
            #pragma unroll
            for (int r = 0; r < 4; r++) s[mt][r] = 0.0f;
        #pragma unroll
        for (int kk = 0; kk < 4; kk++) {
            #pragma unroll
            for (int mt = 0; mt < 4; mt++) {
                const int mc = mh * 32 + mt * 8 + grp;
                float b0 = ks[(kk * 8 + tig) * 72 + mc];
                float b1 = ks[(kk * 8 + tig + 4) * 72 + mc];
                mma_tf32(s[mt], aq[kk], b0, b1);
            }
        }
        // scale + bias
        #pragma unroll
        for (int mt = 0; mt < 4; mt++) {
            const int mg = ch * 64 + mh * 32 + mt * 8 + 2 * tig;
            s[mt][0] = fmaf(s[mt][0], ATT_SCALE, bias_s[abs(ngA - mg)]);
            s[mt][1] = fmaf(s[mt][1], ATT_SCALE, bias_s[abs(ngA - mg - 1)]);
            s[mt][2] = fmaf(s[mt][2], ATT_SCALE, bias_s[abs(ngB - mg)]);
            s[mt][3] = fmaf(s[mt][3], ATT_SCALE, bias_s[abs(ngB - mg - 1)]);
        }
        // partial row max over this m-half
        float mA = -1e30f, mB = -1e30f;
        #pragma unroll
        for (int mt = 0; mt < 4; mt++) {
            mA = fmaxf(mA, fmaxf(s[mt][0], s[mt][1]));
            mB = fmaxf(mB, fmaxf(s[mt][2], s[mt][3]));
        }
        mA = fmaxf(mA, __shfl_xor_sync(0xffffffffu, mA, 1));
        mA = fmaxf(mA, __shfl_xor_sync(0xffffffffu, mA, 2));
        mB = fmaxf(mB, __shfl_xor_sync(0xffffffffu, mB, 1));
        mB = fmaxf(mB, __shfl_xor_sync(0xffffffffu, mB, 2));
        if (tig == 0) { pmax[mh * 128 + rowA] = mA; pmax[mh * 128 + rowB] = mB; }
        __syncthreads();

        // new running max + rescale factor
        float mnA = fmaxf(rmaxA, fmaxf(pmax[rowA], pmax[128 + rowA]));
        float mnB = fmaxf(rmaxB, fmaxf(pmax[rowB], pmax[128 + rowB]));
        float fA = __expf(rmaxA - mnA); rmaxA = mnA;
        float fB = __expf(rmaxB - mnB); rmaxB = mnB;

        // exp, partial sums, write P
        float sA = 0.0f, sB = 0.0f;
        #pragma unroll
        for (int mt = 0; mt < 4; mt++) {
            s[mt][0] = __expf(s[mt][0] - mnA);
            s[mt][1] = __expf(s[mt][1] - mnA);
            s[mt][2] = __expf(s[mt][2] - mnB);
            s[mt][3] = __expf(s[mt][3] - mnB);
            sA += s[mt][0] + s[mt][1];
            sB += s[mt][2] + s[mt][3];
            const int mc = mh * 32 + mt * 8 + 2 * tig;
            *(float2*)&Pbuf[rowA * 68 + mc] = make_float2(s[mt][0], s[mt][1]);
            *(float2*)&Pbuf[rowB * 68 + mc] = make_float2(s[mt][2], s[mt][3]);
        }
        sA += __shfl_xor_sync(0xffffffffu, sA, 1);
        sA += __shfl_xor_sync(0xffffffffu, sA, 2);
        sB += __shfl_xor_sync(0xffffffffu, sB, 1);
        sB += __shfl_xor_sync(0xffffffffu, sB, 2);
        if (tig == 0) { psum[mh * 128 + rowA] = sA; psum[mh * 128 + rowB] = sB; }

        // rescale O accumulators
        #pragma unroll
        for (int j = 0; j < 8; j++) {
            o[j][0] *= fA; o[j][1] *= fA;
            o[j][2] *= fB; o[j][3] *= fB;
        }
        __syncthreads();                      // P + psum visible

        rsumA = rsumA * fA + psum[rowA] + psum[128 + rowA];
        rsumB = rsumB * fB + psum[rowB] + psum[128 + rowB];

        // ---- O += P.V^T : warp's [16 n][64 d] over K = 64 m ----
        const int d0 = mh * 64;
        #pragma unroll
        for (int kk = 0; kk < 8; kk++) {
            float a[4];
            a[0] = Pbuf[rowA * 68 + kk * 8 + tig];
            a[1] = Pbuf[rowB * 68 + kk * 8 + tig];
            a[2] = Pbuf[rowA * 68 + kk * 8 + tig + 4];
            a[3] = Pbuf[rowB * 68 + kk * 8 + tig + 4];
            #pragma unroll
            for (int j = 0; j < 8; j++) {
                const int dc = d0 + j * 8 + grp;
                float b0 = vs[dc * 68 + kk * 8 + tig];
                float b1 = vs[dc * 68 + kk * 8 + tig + 4];
                mma_tf32(o[j], a, b0, b1);
            }
        }
    }

    // ---- epilogue: 1/sum, transpose via smem, relu, store out[d][n] ----
    if (mh == 0 && tig == 0) {
        dinv[rowA] = 1.0f / rsumA;
        dinv[rowB] = 1.0f / rsumB;
    }
    __syncthreads();                          // last PV reads done; reuse stg
    float* Osm = sh + FOSM_OFF;               // [128 n][stride 129]
    {
        const int d0 = mh * 64;
        #pragma unroll
        for (int j = 0; j < 8; j++) {
            const int dc = d0 + j * 8 + 2 * tig;
            Osm[rowA * 129 + dc]     = o[j][0];
            Osm[rowA * 129 + dc + 1] = o[j][1];
            Osm[rowB * 129 + dc]     = o[j][2];
            Osm[rowB * 129 + dc + 1] = o[j][3];
        }
    }
    __syncthreads();
    {
        const int d  = t >> 2;
        const int ns = (t & 3) * 32;
        float* ob = outp + ((size_t)b * DHDIM + h * DV + d) * RES + n0;
        #pragma unroll
        for (int i = 0; i < 8; i++) {
            const int n = ns + i * 4;
            float4 w;
            w.x = fmaxf(Osm[(n + 0) * 129 + d] * dinv[n + 0], 0.0f);
            w.y = fmaxf(Osm[(n + 1) * 129 + d] * dinv[n + 1], 0.0f);
            w.z = fmaxf(Osm[(n + 2) * 129 + d] * dinv[n + 2], 0.0f);
            w.w = fmaxf(Osm[(n + 3) * 129 + d] * dinv[n + 3], 0.0f);
            *(float4*)&ob[n] = w;
        }
    }
}

// --------------------------------- launch -------------------------------------
extern "C" void kernel_launch(void* const* d_in, const int* in_sizes, int n_in,
                              void* d_out, int out_size)
{
    const float* x      = (const float*)d_in[0];
    const float* w_qkv  = (const float*)d_in[1];
    const float* qkv_g  = (const float*)d_in[2];
    const float* qkv_b  = (const float*)d_in[3];
    const float* qkv_m  = (const float*)d_in[4];
    const float* qkv_v  = (const float*)d_in[5];
    const float* w_dw   = (const float*)d_in[6];
    const float* dw_g   = (const float*)d_in[7];
    const float* dw_b   = (const float*)d_in[8];
    const float* dw_m   = (const float*)d_in[9];
    const float* dw_v   = (const float*)d_in[10];
    const float* w_proj = (const float*)d_in[11];
    const float* proj_g = (const float*)d_in[12];
    const float* proj_b = (const float*)d_in[13];
    const float* proj_m = (const float*)d_in[14];
    const float* proj_v = (const float*)d_in[15];
    const float* att_bias = (const float*)d_in[16];

    float *p_qkv, *p_q, *p_att;
    cudaGetSymbolAddress((void**)&p_qkv, g_qkv);
    cudaGetSymbolAddress((void**)&p_q,   g_q);
    cudaGetSymbolAddress((void**)&p_att, g_att);

    cudaFuncSetAttribute(gemm_tf32_bn, cudaFuncAttributeMaxDynamicSharedMemorySize,
                         GEMM_SMEM_BYTES);
    cudaFuncSetAttribute(flash_attn_kernel, cudaFuncAttributeMaxDynamicSharedMemorySize,
                         FLASH_SMEM_BYTES);

    gemm_tf32_bn<<<dim3(RES / 128, HQKV / 128, BATCH), 256, GEMM_SMEM_BYTES>>>(
        w_qkv, x, qkv_g, qkv_b, qkv_m, qkv_v, p_qkv, HQKV, DIMC, RES);

    dwconv_bn_kernel<<<(BATCH * NHKD * RES) / 256, 256>>>(
        p_qkv, w_dw, dw_g, dw_b, dw_m, dw_v, p_q);

    flash_attn_kernel<<<dim3(RES / 128, NHEAD, BATCH), 512, FLASH_SMEM_BYTES>>>(
        p_q, p_qkv, att_bias, p_att);

    gemm_tf32_bn<<<dim3(RES / 128, DIMC / 128, BATCH), 256, GEMM_SMEM_BYTES>>>(
        w_proj, p_att, proj_g, proj_b, proj_m, proj_v, (float*)d_out,
        DIMC, DHDIM, RES);
}